// round 1
// baseline (speedup 1.0000x reference)
#include <cuda_runtime.h>
#include <cstdint>

#define DIMM   4096
#define KVDIM  1024
#define SEQ    2048
#define NBATCH 2
#define NHEAD  32
#define HD     128

// Scratch (static device globals -- allocation-guard safe)
__device__ float g_q[(size_t)NBATCH * SEQ * DIMM];   // 64 MB
__device__ float g_k[(size_t)NBATCH * SEQ * KVDIM];  // 16 MB
__device__ float g_v[(size_t)NBATCH * SEQ * KVDIM];  // 16 MB
__device__ float g_o[(size_t)NBATCH * SEQ * DIMM];   // 64 MB

__device__ __forceinline__ unsigned f2tf(float x) {
    unsigned u;
    asm("cvt.rna.tf32.f32 %0, %1;" : "=r"(u) : "f"(x));
    return u;
}
__device__ __forceinline__ float tf32f(float x) { return __uint_as_float(f2tf(x)); }

__device__ __forceinline__ void mma_tf32(float* d,
                                         unsigned a0, unsigned a1, unsigned a2, unsigned a3,
                                         unsigned b0, unsigned b1) {
    asm volatile(
        "mma.sync.aligned.m16n8k8.row.col.f32.tf32.tf32.f32 "
        "{%0,%1,%2,%3},{%4,%5,%6,%7},{%8,%9},{%0,%1,%2,%3};"
        : "+f"(d[0]), "+f"(d[1]), "+f"(d[2]), "+f"(d[3])
        : "r"(a0), "r"(a1), "r"(a2), "r"(a3), "r"(b0), "r"(b1));
}

// ============================================================================
// Generic GEMM: C[M,N] = A[M,K] @ B[K,N], all row-major fp32, tf32 tensor cores.
// CTA tile 128x128, k-tile 32, 256 threads = 8 warps (4m x 2n), warp tile 32x64.
// ============================================================================
#define GA_STRIDE 36    // 32 + 4 pad: A-frag loads conflict-free
#define GB_STRIDE 136   // 128 + 8 pad: B-frag loads conflict-free

__global__ void __launch_bounds__(256) gemm_tf32_kernel(
    const float* __restrict__ A, const float* __restrict__ B, float* __restrict__ C,
    int M, int N, int K)
{
    extern __shared__ float smbuf[];
    float* As = smbuf;                         // [2][128*36]
    float* Bs = smbuf + 2 * 128 * GA_STRIDE;   // [2][32*136]

    const int tid = threadIdx.x;
    const int warp = tid >> 5, lane = tid & 31;
    const int wm = warp >> 1, wn = warp & 1;
    const int g = lane >> 2, q = lane & 3;
    const long brow = (long)blockIdx.y * 128;
    const long bcol = (long)blockIdx.x * 128;

    float acc[2][8][4];
#pragma unroll
    for (int i = 0; i < 2; i++)
#pragma unroll
        for (int j = 0; j < 8; j++)
#pragma unroll
            for (int k = 0; k < 4; k++) acc[i][j][k] = 0.f;

    float4 ra[4], rb[4];
    const int nkt = K / 32;

    auto gload = [&](int kt) {
#pragma unroll
        for (int i = 0; i < 4; i++) {
            int f = tid + i * 256;
            ra[i] = *(const float4*)&A[(brow + (f >> 3)) * K + kt * 32 + (f & 7) * 4];
        }
#pragma unroll
        for (int i = 0; i < 4; i++) {
            int f = tid + i * 256;
            rb[i] = *(const float4*)&B[((long)kt * 32 + (f >> 5)) * N + bcol + (f & 31) * 4];
        }
    };
    auto sstore = [&](int s) {
#pragma unroll
        for (int i = 0; i < 4; i++) {
            int f = tid + i * 256;
            float4 v = ra[i];
            *(float4*)&As[s * 128 * GA_STRIDE + (f >> 3) * GA_STRIDE + (f & 7) * 4] =
                make_float4(tf32f(v.x), tf32f(v.y), tf32f(v.z), tf32f(v.w));
        }
#pragma unroll
        for (int i = 0; i < 4; i++) {
            int f = tid + i * 256;
            float4 v = rb[i];
            *(float4*)&Bs[s * 32 * GB_STRIDE + (f >> 5) * GB_STRIDE + (f & 31) * 4] =
                make_float4(tf32f(v.x), tf32f(v.y), tf32f(v.z), tf32f(v.w));
        }
    };

    gload(0);
    sstore(0);
    __syncthreads();

    for (int kt = 0; kt < nkt; kt++) {
        int s = kt & 1;
        if (kt + 1 < nkt) gload(kt + 1);

        const float* as = &As[s * 128 * GA_STRIDE];
        const float* bs = &Bs[s * 32 * GB_STRIDE];
#pragma unroll
        for (int ks = 0; ks < 4; ks++) {
            unsigned af[2][4];
#pragma unroll
            for (int mt = 0; mt < 2; mt++) {
                int r0 = wm * 32 + mt * 16 + g;
                af[mt][0] = __float_as_uint(as[r0 * GA_STRIDE + ks * 8 + q]);
                af[mt][1] = __float_as_uint(as[(r0 + 8) * GA_STRIDE + ks * 8 + q]);
                af[mt][2] = __float_as_uint(as[r0 * GA_STRIDE + ks * 8 + q + 4]);
                af[mt][3] = __float_as_uint(as[(r0 + 8) * GA_STRIDE + ks * 8 + q + 4]);
            }
#pragma unroll
            for (int nt = 0; nt < 8; nt++) {
                int c0 = wn * 64 + nt * 8 + g;
                unsigned b0 = __float_as_uint(bs[(ks * 8 + q) * GB_STRIDE + c0]);
                unsigned b1 = __float_as_uint(bs[(ks * 8 + q + 4) * GB_STRIDE + c0]);
                mma_tf32(acc[0][nt], af[0][0], af[0][1], af[0][2], af[0][3], b0, b1);
                mma_tf32(acc[1][nt], af[1][0], af[1][1], af[1][2], af[1][3], b0, b1);
            }
        }
        if (kt + 1 < nkt) sstore(1 - s);
        __syncthreads();
    }

#pragma unroll
    for (int mt = 0; mt < 2; mt++) {
        long r0 = brow + wm * 32 + mt * 16 + g;
#pragma unroll
        for (int nt = 0; nt < 8; nt++) {
            long c = bcol + wn * 64 + nt * 8 + q * 2;
            *(float2*)&C[r0 * N + c]       = make_float2(acc[mt][nt][0], acc[mt][nt][1]);
            *(float2*)&C[(r0 + 8) * N + c] = make_float2(acc[mt][nt][2], acc[mt][nt][3]);
        }
    }
}

// ============================================================================
// Flash attention: CTA = 128 q-rows of one (batch, head). 8 warps x 16 rows.
// Online softmax, Q fragments register-resident, K/V tiles in padded smem.
// ============================================================================
#define KS_STRIDE 132   // 128 + 4 : QK B-frag loads conflict-free
#define VS_STRIDE 136   // 128 + 8 : PV B-frag loads conflict-free

__global__ void __launch_bounds__(256) attn_kernel()
{
    extern __shared__ float smbuf[];
    float* Ksm = smbuf;                    // 128*132 (also used for Q staging)
    float* Vsm = smbuf + 128 * KS_STRIDE;  // 128*136

    const int tid = threadIdx.x, warp = tid >> 5, lane = tid & 31;
    const int g = lane >> 2, q = lane & 3;
    const int qt = blockIdx.x, h = blockIdx.y, b = blockIdx.z;
    const int kvh = h >> 2;  // n_rep = 4 (repeat_interleave)
    const float scale = 0.08838834764831845f;  // 1/sqrt(128), folded into Q

    // --- Stage Q (scaled, tf32-rounded), then load A-fragments to registers ---
    const float* qbase = g_q + ((size_t)b * SEQ + (size_t)qt * 128) * DIMM + h * HD;
#pragma unroll
    for (int i = 0; i < 16; i++) {
        int f = tid + i * 256;
        int r = f >> 5, c4 = f & 31;
        float4 v = *(const float4*)&qbase[(size_t)r * DIMM + c4 * 4];
        *(float4*)&Ksm[r * KS_STRIDE + c4 * 4] =
            make_float4(tf32f(v.x * scale), tf32f(v.y * scale),
                        tf32f(v.z * scale), tf32f(v.w * scale));
    }
    __syncthreads();

    unsigned qa[16][4];
    {
        int r0 = warp * 16 + g;
#pragma unroll
        for (int ks = 0; ks < 16; ks++) {
            qa[ks][0] = __float_as_uint(Ksm[r0 * KS_STRIDE + ks * 8 + q]);
            qa[ks][1] = __float_as_uint(Ksm[(r0 + 8) * KS_STRIDE + ks * 8 + q]);
            qa[ks][2] = __float_as_uint(Ksm[r0 * KS_STRIDE + ks * 8 + q + 4]);
            qa[ks][3] = __float_as_uint(Ksm[(r0 + 8) * KS_STRIDE + ks * 8 + q + 4]);
        }
    }

    float oacc[16][4];
#pragma unroll
    for (int i = 0; i < 16; i++)
#pragma unroll
        for (int j = 0; j < 4; j++) oacc[i][j] = 0.f;
    float m0 = -1e30f, m1 = -1e30f, l0 = 0.f, l1 = 0.f;

    const float* kbase = g_k + (size_t)b * SEQ * KVDIM + kvh * HD;
    const float* vbase = g_v + (size_t)b * SEQ * KVDIM + kvh * HD;

    for (int kt = 0; kt < 16; kt++) {
        __syncthreads();  // previous tile (or Q frags) fully consumed
#pragma unroll
        for (int i = 0; i < 16; i++) {
            int f = tid + i * 256;
            int r = f >> 5, c4 = f & 31;
            float4 v = *(const float4*)&kbase[((size_t)(kt * 128 + r)) * KVDIM + c4 * 4];
            *(float4*)&Ksm[r * KS_STRIDE + c4 * 4] =
                make_float4(tf32f(v.x), tf32f(v.y), tf32f(v.z), tf32f(v.w));
        }
#pragma unroll
        for (int i = 0; i < 16; i++) {
            int f = tid + i * 256;
            int r = f >> 5, c4 = f & 31;
            float4 v = *(const float4*)&vbase[((size_t)(kt * 128 + r)) * KVDIM + c4 * 4];
            *(float4*)&Vsm[r * VS_STRIDE + c4 * 4] =
                make_float4(tf32f(v.x), tf32f(v.y), tf32f(v.z), tf32f(v.w));
        }
        __syncthreads();

        // ---- S = Q @ K^T (scaled) ----
        float sacc[16][4];
#pragma unroll
        for (int i = 0; i < 16; i++)
#pragma unroll
            for (int j = 0; j < 4; j++) sacc[i][j] = 0.f;
#pragma unroll
        for (int nt = 0; nt < 16; nt++) {
#pragma unroll
            for (int ks = 0; ks < 16; ks++) {
                unsigned b0 = __float_as_uint(Ksm[(nt * 8 + g) * KS_STRIDE + ks * 8 + q]);
                unsigned b1 = __float_as_uint(Ksm[(nt * 8 + g) * KS_STRIDE + ks * 8 + q + 4]);
                mma_tf32(sacc[nt], qa[ks][0], qa[ks][1], qa[ks][2], qa[ks][3], b0, b1);
            }
        }

        // ---- online softmax (rows g and g+8 of this warp's 16) ----
        float tm0 = -1e30f, tm1 = -1e30f;
#pragma unroll
        for (int nt = 0; nt < 16; nt++) {
            tm0 = fmaxf(tm0, fmaxf(sacc[nt][0], sacc[nt][1]));
            tm1 = fmaxf(tm1, fmaxf(sacc[nt][2], sacc[nt][3]));
        }
        tm0 = fmaxf(tm0, __shfl_xor_sync(0xffffffffu, tm0, 1));
        tm0 = fmaxf(tm0, __shfl_xor_sync(0xffffffffu, tm0, 2));
        tm1 = fmaxf(tm1, __shfl_xor_sync(0xffffffffu, tm1, 1));
        tm1 = fmaxf(tm1, __shfl_xor_sync(0xffffffffu, tm1, 2));

        float mn0 = fmaxf(m0, tm0), mn1 = fmaxf(m1, tm1);
        float al0 = __expf(m0 - mn0), al1 = __expf(m1 - mn1);
        m0 = mn0; m1 = mn1;

        float rs0 = 0.f, rs1 = 0.f;
#pragma unroll
        for (int nt = 0; nt < 16; nt++) {
            sacc[nt][0] = __expf(sacc[nt][0] - mn0); rs0 += sacc[nt][0];
            sacc[nt][1] = __expf(sacc[nt][1] - mn0); rs0 += sacc[nt][1];
            sacc[nt][2] = __expf(sacc[nt][2] - mn1); rs1 += sacc[nt][2];
            sacc[nt][3] = __expf(sacc[nt][3] - mn1); rs1 += sacc[nt][3];
        }
        rs0 += __shfl_xor_sync(0xffffffffu, rs0, 1);
        rs0 += __shfl_xor_sync(0xffffffffu, rs0, 2);
        rs1 += __shfl_xor_sync(0xffffffffu, rs1, 1);
        rs1 += __shfl_xor_sync(0xffffffffu, rs1, 2);
        l0 = l0 * al0 + rs0;
        l1 = l1 * al1 + rs1;

#pragma unroll
        for (int nt = 0; nt < 16; nt++) {
            oacc[nt][0] *= al0; oacc[nt][1] *= al0;
            oacc[nt][2] *= al1; oacc[nt][3] *= al1;
        }

        // ---- O += P @ V  (C-layout -> A-layout via intra-quad shuffles) ----
#pragma unroll
        for (int ks = 0; ks < 16; ks++) {
            float c0 = sacc[ks][0], c1 = sacc[ks][1], c2 = sacc[ks][2], c3 = sacc[ks][3];
            int srcL = (lane & 28) | (q >> 1);
            int srcH = srcL + 2;
            float x0 = __shfl_sync(0xffffffffu, c0, srcL);
            float x1 = __shfl_sync(0xffffffffu, c1, srcL);
            float y0 = __shfl_sync(0xffffffffu, c0, srcH);
            float y1 = __shfl_sync(0xffffffffu, c1, srcH);
            float z0 = __shfl_sync(0xffffffffu, c2, srcL);
            float z1 = __shfl_sync(0xffffffffu, c3, srcL);
            float w0 = __shfl_sync(0xffffffffu, c2, srcH);
            float w1 = __shfl_sync(0xffffffffu, c3, srcH);
            bool od = (q & 1);
            unsigned pa0 = f2tf(od ? x1 : x0);
            unsigned pa1 = f2tf(od ? z1 : z0);
            unsigned pa2 = f2tf(od ? y1 : y0);
            unsigned pa3 = f2tf(od ? w1 : w0);
#pragma unroll
            for (int nt = 0; nt < 16; nt++) {
                unsigned b0 = __float_as_uint(Vsm[(ks * 8 + q) * VS_STRIDE + nt * 8 + g]);
                unsigned b1 = __float_as_uint(Vsm[(ks * 8 + q + 4) * VS_STRIDE + nt * 8 + g]);
                mma_tf32(oacc[nt], pa0, pa1, pa2, pa3, b0, b1);
            }
        }
    }

    // ---- epilogue: O / l -> g_o[b, s, h*128 + d] ----
    float il0 = 1.f / l0, il1 = 1.f / l1;
    float* ob = g_o + ((size_t)b * SEQ + (size_t)qt * 128 + warp * 16) * DIMM + h * HD;
#pragma unroll
    for (int nt = 0; nt < 16; nt++) {
        int c = nt * 8 + q * 2;
        *(float2*)&ob[(size_t)g * DIMM + c] =
            make_float2(oacc[nt][0] * il0, oacc[nt][1] * il0);
        *(float2*)&ob[(size_t)(g + 8) * DIMM + c] =
            make_float2(oacc[nt][2] * il1, oacc[nt][3] * il1);
    }
}

// ============================================================================
extern "C" void kernel_launch(void* const* d_in, const int* in_sizes, int n_in,
                              void* d_out, int out_size)
{
    const float* x  = (const float*)d_in[0];
    const float* wq = (const float*)d_in[1];
    const float* wk = (const float*)d_in[2];
    const float* wv = (const float*)d_in[3];
    const float* wo = (const float*)d_in[4];
    float* out = (float*)d_out;

    float *qb, *kb, *vb, *ob;
    cudaGetSymbolAddress((void**)&qb, g_q);
    cudaGetSymbolAddress((void**)&kb, g_k);
    cudaGetSymbolAddress((void**)&vb, g_v);
    cudaGetSymbolAddress((void**)&ob, g_o);

    const int GEMM_SMEM = (2 * 128 * GA_STRIDE + 2 * 32 * GB_STRIDE) * (int)sizeof(float);
    const int ATTN_SMEM = (128 * KS_STRIDE + 128 * VS_STRIDE) * (int)sizeof(float);
    cudaFuncSetAttribute(gemm_tf32_kernel, cudaFuncAttributeMaxDynamicSharedMemorySize, GEMM_SMEM);
    cudaFuncSetAttribute(attn_kernel, cudaFuncAttributeMaxDynamicSharedMemorySize, ATTN_SMEM);

    const int M = NBATCH * SEQ;  // 4096 token rows

    gemm_tf32_kernel<<<dim3(DIMM / 128, M / 128), 256, GEMM_SMEM>>>(x, wq, qb, M, DIMM, DIMM);
    gemm_tf32_kernel<<<dim3(KVDIM / 128, M / 128), 256, GEMM_SMEM>>>(x, wk, kb, M, KVDIM, DIMM);
    gemm_tf32_kernel<<<dim3(KVDIM / 128, M / 128), 256, GEMM_SMEM>>>(x, wv, vb, M, KVDIM, DIMM);

    attn_kernel<<<dim3(SEQ / 128, NHEAD, NBATCH), 256, ATTN_SMEM>>>();

    gemm_tf32_kernel<<<dim3(DIMM / 128, M / 128), 256, GEMM_SMEM>>>(ob, wo, out, M, DIMM, DIMM);
}

// round 3
// speedup vs baseline: 2.2948x; 2.2948x over previous
#include <cuda_runtime.h>
#include <cuda_fp16.h>
#include <cstdint>

#define DIMM   4096
#define KVDIM  1024
#define SEQ    2048
#define NBATCH 2
#define NHEAD  32
#define HD     128
#define MROWS  (NBATCH * SEQ)   // 4096 token rows

// ---------------------------------------------------------------------------
// Scratch (static device globals -- allocation-guard safe), all fp16
// ---------------------------------------------------------------------------
__device__ __half g_xh [(size_t)MROWS * DIMM];    // x converted
__device__ __half g_qh [(size_t)MROWS * DIMM];    // q (scale folded into wq)
__device__ __half g_kh [(size_t)MROWS * KVDIM];
__device__ __half g_vh [(size_t)MROWS * KVDIM];
__device__ __half g_oh [(size_t)MROWS * DIMM];    // attention out
__device__ __half g_wqt[(size_t)DIMM * DIMM];     // wq^T * scale  [N,K]
__device__ __half g_wkt[(size_t)KVDIM * DIMM];
__device__ __half g_wvt[(size_t)KVDIM * DIMM];
__device__ __half g_wot[(size_t)DIMM * DIMM];

// ---------------------------------------------------------------------------
// Helpers
// ---------------------------------------------------------------------------
__device__ __forceinline__ uint32_t smem_u32(const void* p) {
    uint32_t a;
    asm("{ .reg .u64 t; cvta.to.shared.u64 t, %1; cvt.u32.u64 %0, t; }" : "=r"(a) : "l"(p));
    return a;
}

__device__ __forceinline__ void mma_f16(float* d, uint32_t a0, uint32_t a1,
                                        uint32_t a2, uint32_t a3,
                                        uint32_t b0, uint32_t b1) {
    asm volatile(
        "mma.sync.aligned.m16n8k16.row.col.f32.f16.f16.f32 "
        "{%0,%1,%2,%3},{%4,%5,%6,%7},{%8,%9},{%0,%1,%2,%3};"
        : "+f"(d[0]), "+f"(d[1]), "+f"(d[2]), "+f"(d[3])
        : "r"(a0), "r"(a1), "r"(a2), "r"(a3), "r"(b0), "r"(b1));
}

__device__ __forceinline__ void ldsm_x4(uint32_t& r0, uint32_t& r1,
                                        uint32_t& r2, uint32_t& r3, uint32_t addr) {
    asm volatile("ldmatrix.sync.aligned.m8n8.x4.shared.b16 {%0,%1,%2,%3}, [%4];"
                 : "=r"(r0), "=r"(r1), "=r"(r2), "=r"(r3) : "r"(addr));
}
__device__ __forceinline__ void ldsm_x4_t(uint32_t& r0, uint32_t& r1,
                                          uint32_t& r2, uint32_t& r3, uint32_t addr) {
    asm volatile("ldmatrix.sync.aligned.m8n8.x4.trans.shared.b16 {%0,%1,%2,%3}, [%4];"
                 : "=r"(r0), "=r"(r1), "=r"(r2), "=r"(r3) : "r"(addr));
}

__device__ __forceinline__ uint32_t pack_h2(float lo, float hi) {
    __half2 h = __floats2half2_rn(lo, hi);
    return *(uint32_t*)&h;
}

#define CP16(dst, src) \
    asm volatile("cp.async.cg.shared.global [%0], [%1], 16;" :: "r"(dst), "l"(src))
#define CP_COMMIT() asm volatile("cp.async.commit_group;")

// ---------------------------------------------------------------------------
// Pre-pass kernels
// ---------------------------------------------------------------------------
__global__ void conv_half_kernel(const float4* __restrict__ src,
                                 uint2* __restrict__ dst, int n4) {
    int i = blockIdx.x * blockDim.x + threadIdx.x;
    if (i < n4) {
        float4 v = src[i];
        uint2 u;
        u.x = pack_h2(v.x, v.y);
        u.y = pack_h2(v.z, v.w);
        dst[i] = u;
    }
}

// dst[C x R] (half) = mul * src[R x C]^T
__global__ void transpose_half_kernel(const float* __restrict__ src,
                                      __half* __restrict__ dst, int R, int C,
                                      float mul) {
    __shared__ float t[32][33];
    int bx = blockIdx.x * 32, by = blockIdx.y * 32;
    int x = bx + threadIdx.x;
#pragma unroll
    for (int i = threadIdx.y; i < 32; i += 8)
        t[i][threadIdx.x] = src[(size_t)(by + i) * C + x];
    __syncthreads();
    int ox = by + threadIdx.x;
#pragma unroll
    for (int i = threadIdx.y; i < 32; i += 8)
        dst[(size_t)(bx + i) * R + ox] = __float2half(t[threadIdx.x][i] * mul);
}

// ---------------------------------------------------------------------------
// fp16 GEMM: C[M,N] = A[M,K] @ Bt[N,K]^T.  CTA 128x128, k-tile 32, 4-stage
// cp.async, 8 warps (4m x 2n), warp tile 32x64, mma m16n8k16, fp32 accum.
// ---------------------------------------------------------------------------
#define GST   40                 // smem row stride (halves): 32 + 8 pad
#define ASTH  (128 * GST)        // halves per stage per operand
#define NST   4
#define GEMM_SMEM (NST * 2 * ASTH * 2)   // bytes = 81920

template <typename OutT>
__global__ void __launch_bounds__(256) gemm_f16_kernel(
    const __half* __restrict__ A, const __half* __restrict__ Bt,
    OutT* __restrict__ C, int M, int N, int K)
{
    extern __shared__ __half sm[];
    __half* As = sm;
    __half* Bs = sm + NST * ASTH;
    const uint32_t smA = smem_u32(As), smB = smem_u32(Bs);

    const int tid = threadIdx.x, warp = tid >> 5, lane = tid & 31;
    const int wm = warp >> 1, wn = warp & 1;
    const int g = lane >> 2, q = lane & 3;
    const long brow = (long)blockIdx.y * 128;
    const long bcol = (long)blockIdx.x * 128;

    float acc[2][8][4];
#pragma unroll
    for (int i = 0; i < 2; i++)
#pragma unroll
        for (int j = 0; j < 8; j++)
#pragma unroll
            for (int k = 0; k < 4; k++) acc[i][j][k] = 0.f;

    // global/smem addresses for cp.async (2 chunks per thread per operand)
    const int r_ld = tid >> 2, c_ld = tid & 3;     // +64 rows for second chunk
    const __half* gA0 = A + (brow + r_ld) * (long)K + c_ld * 8;
    const __half* gB0 = Bt + (bcol + r_ld) * (long)K + c_ld * 8;
    const uint32_t sA0 = smA + (r_ld * GST + c_ld * 8) * 2;
    const uint32_t sB0 = smB + (r_ld * GST + c_ld * 8) * 2;
    const long rowK64 = 64 * (long)K;

    const int NKT = K >> 5;

#define G_LOAD(s, kt) do {                                                   \
        uint32_t so = (uint32_t)(s) * (ASTH * 2);                            \
        long go = (long)(kt) * 32;                                           \
        CP16(sA0 + so,                 gA0 + go);                            \
        CP16(sA0 + so + 64 * GST * 2,  gA0 + go + rowK64);                   \
        CP16(sB0 + so,                 gB0 + go);                            \
        CP16(sB0 + so + 64 * GST * 2,  gB0 + go + rowK64);                   \
    } while (0)

    for (int s = 0; s < NST - 1; s++) { G_LOAD(s, s); CP_COMMIT(); }

    // fragment base addresses (bytes)
    uint32_t aAddr[2], bAddr[4];
#pragma unroll
    for (int mt = 0; mt < 2; mt++)
        aAddr[mt] = smA + (((wm * 32 + mt * 16 + (lane & 15)) * GST) +
                           ((lane & 16) ? 8 : 0)) * 2;
#pragma unroll
    for (int np = 0; np < 4; np++)
        bAddr[np] = smB + (((wn * 64 + np * 16 + (lane & 7) + ((lane & 16) ? 8 : 0)) * GST) +
                           ((lane & 8) ? 8 : 0)) * 2;

    for (int kt = 0; kt < NKT; kt++) {
        const int s = kt & (NST - 1);
        asm volatile("cp.async.wait_group 2;");
        __syncthreads();
        const int nxt = kt + NST - 1;
        if (nxt < NKT) G_LOAD(nxt & (NST - 1), nxt);
        CP_COMMIT();

        const uint32_t so = (uint32_t)s * (ASTH * 2);
#pragma unroll
        for (int ks = 0; ks < 2; ks++) {
            uint32_t af[2][4];
#pragma unroll
            for (int mt = 0; mt < 2; mt++)
                ldsm_x4(af[mt][0], af[mt][1], af[mt][2], af[mt][3],
                        aAddr[mt] + so + ks * 32);
#pragma unroll
            for (int np = 0; np < 4; np++) {
                uint32_t b0, b1, b2, b3;
                ldsm_x4(b0, b1, b2, b3, bAddr[np] + so + ks * 32);
                mma_f16(acc[0][2 * np],     af[0][0], af[0][1], af[0][2], af[0][3], b0, b1);
                mma_f16(acc[1][2 * np],     af[1][0], af[1][1], af[1][2], af[1][3], b0, b1);
                mma_f16(acc[0][2 * np + 1], af[0][0], af[0][1], af[0][2], af[0][3], b2, b3);
                mma_f16(acc[1][2 * np + 1], af[1][0], af[1][1], af[1][2], af[1][3], b2, b3);
            }
        }
    }

#pragma unroll
    for (int mt = 0; mt < 2; mt++) {
        long r0 = brow + wm * 32 + mt * 16 + g;
#pragma unroll
        for (int nt = 0; nt < 8; nt++) {
            long c = bcol + wn * 64 + nt * 8 + q * 2;
            if constexpr (sizeof(OutT) == 2) {
                *(uint32_t*)&C[r0 * N + c]       = pack_h2(acc[mt][nt][0], acc[mt][nt][1]);
                *(uint32_t*)&C[(r0 + 8) * N + c] = pack_h2(acc[mt][nt][2], acc[mt][nt][3]);
            } else {
                *(float2*)&C[r0 * N + c]       = make_float2(acc[mt][nt][0], acc[mt][nt][1]);
                *(float2*)&C[(r0 + 8) * N + c] = make_float2(acc[mt][nt][2], acc[mt][nt][3]);
            }
        }
    }
}

// ---------------------------------------------------------------------------
// Flash attention, fp16. CTA = 128 q-rows x one (b,h). 8 warps x 16 rows.
// K/V tiles double-buffered via cp.async. PV A-operand direct from C-layout.
// ---------------------------------------------------------------------------
#define AST2   136                      // attn smem row stride (halves)
#define TILEH  (128 * AST2)             // halves per tile buffer
#define ATTN_SMEM (4 * TILEH * 2)       // K0,K1,V0,V1 = 139264 B

__global__ void __launch_bounds__(256) attn_kernel()
{
    extern __shared__ __half sm[];
    const uint32_t smK0 = smem_u32(sm);                  // buf stride TILEH*2 bytes
    const uint32_t smV0 = smK0 + 2 * TILEH * 2;

    const int tid = threadIdx.x, warp = tid >> 5, lane = tid & 31;
    const int g = lane >> 2, q = lane & 3;
    const int qt = blockIdx.x, h = blockIdx.y, b = blockIdx.z;
    const int kvh = h >> 2;

    // ---- stage Q tile into K-buf0, then load A-fragments ----
    {
        const __half* qbase = g_qh + ((size_t)b * SEQ + (size_t)qt * 128) * DIMM + h * HD;
        __half* Qs = sm;
#pragma unroll
        for (int i = 0; i < 8; i++) {
            int f = tid + i * 256;
            int r = f >> 4, c = f & 15;
            *(uint4*)&Qs[r * AST2 + c * 8] = *(const uint4*)&qbase[(size_t)r * DIMM + c * 8];
        }
    }
    __syncthreads();

    uint32_t qa[8][4];
    {
        uint32_t qaddr = smK0 + (((warp * 16 + (lane & 15)) * AST2) +
                                 ((lane & 16) ? 8 : 0)) * 2;
#pragma unroll
        for (int ks = 0; ks < 8; ks++)
            ldsm_x4(qa[ks][0], qa[ks][1], qa[ks][2], qa[ks][3], qaddr + ks * 32);
    }
    __syncthreads();   // frags read before cp.async overwrites buf0

    // ---- cp.async K/V tile loaders ----
    const int r_ld = tid >> 1, c_ld = tid & 1;  // 128 rows x 2 half-rows? no:
    // 128 rows x 16 chunks = 2048 chunks, 8 per thread: r = f>>4, c = f&15
    const __half* kbase = g_kh + (size_t)b * SEQ * KVDIM + kvh * HD;
    const __half* vbase = g_vh + (size_t)b * SEQ * KVDIM + kvh * HD;
    (void)r_ld; (void)c_ld;

#define KV_LOAD(kt, buf) do {                                                   \
        uint32_t kd = smK0 + (uint32_t)(buf) * (TILEH * 2);                     \
        uint32_t vd = smV0 + (uint32_t)(buf) * (TILEH * 2);                     \
        size_t rowoff = (size_t)(kt) * 128;                                     \
        _Pragma("unroll")                                                       \
        for (int i = 0; i < 8; i++) {                                           \
            int f = tid + i * 256;                                              \
            int r = f >> 4, c = f & 15;                                         \
            CP16(kd + (r * AST2 + c * 8) * 2,                                   \
                 kbase + (rowoff + r) * KVDIM + c * 8);                         \
            CP16(vd + (r * AST2 + c * 8) * 2,                                   \
                 vbase + (rowoff + r) * KVDIM + c * 8);                         \
        }                                                                       \
    } while (0)

    KV_LOAD(0, 0); CP_COMMIT();
    KV_LOAD(1, 1); CP_COMMIT();

    float oacc[16][4];
#pragma unroll
    for (int i = 0; i < 16; i++)
#pragma unroll
        for (int j = 0; j < 4; j++) oacc[i][j] = 0.f;
    float m0 = -1e30f, m1 = -1e30f, l0 = 0.f, l1 = 0.f;

    // fragment base offsets (bytes, buffer-relative)
    const uint32_t kBase = (((lane & 7) + ((lane & 16) ? 8 : 0)) * AST2 +
                            ((lane & 8) ? 8 : 0)) * 2;
    const uint32_t vBase = ((lane & 15) * AST2 + ((lane & 16) ? 8 : 0)) * 2;

    for (int kt = 0; kt < 16; kt++) {
        asm volatile("cp.async.wait_group 1;");
        __syncthreads();
        const uint32_t kb = smK0 + (uint32_t)(kt & 1) * (TILEH * 2);
        const uint32_t vb = smV0 + (uint32_t)(kt & 1) * (TILEH * 2);

        // ---- S = Q @ K^T ----
        float sacc[16][4];
#pragma unroll
        for (int i = 0; i < 16; i++)
#pragma unroll
            for (int j = 0; j < 4; j++) sacc[i][j] = 0.f;
#pragma unroll
        for (int ks = 0; ks < 8; ks++) {
#pragma unroll
            for (int np = 0; np < 8; np++) {
                uint32_t b0, b1, b2, b3;
                ldsm_x4(b0, b1, b2, b3, kb + kBase + np * (16 * AST2 * 2) + ks * 32);
                mma_f16(sacc[2 * np],     qa[ks][0], qa[ks][1], qa[ks][2], qa[ks][3], b0, b1);
                mma_f16(sacc[2 * np + 1], qa[ks][0], qa[ks][1], qa[ks][2], qa[ks][3], b2, b3);
            }
        }

        // ---- online softmax (rows g and g+8) ----
        float tm0 = -1e30f, tm1 = -1e30f;
#pragma unroll
        for (int nt = 0; nt < 16; nt++) {
            tm0 = fmaxf(tm0, fmaxf(sacc[nt][0], sacc[nt][1]));
            tm1 = fmaxf(tm1, fmaxf(sacc[nt][2], sacc[nt][3]));
        }
        tm0 = fmaxf(tm0, __shfl_xor_sync(0xffffffffu, tm0, 1));
        tm0 = fmaxf(tm0, __shfl_xor_sync(0xffffffffu, tm0, 2));
        tm1 = fmaxf(tm1, __shfl_xor_sync(0xffffffffu, tm1, 1));
        tm1 = fmaxf(tm1, __shfl_xor_sync(0xffffffffu, tm1, 2));

        float mn0 = fmaxf(m0, tm0), mn1 = fmaxf(m1, tm1);
        float al0 = __expf(m0 - mn0), al1 = __expf(m1 - mn1);
        m0 = mn0; m1 = mn1;

        float rs0 = 0.f, rs1 = 0.f;
#pragma unroll
        for (int nt = 0; nt < 16; nt++) {
            sacc[nt][0] = __expf(sacc[nt][0] - mn0); rs0 += sacc[nt][0];
            sacc[nt][1] = __expf(sacc[nt][1] - mn0); rs0 += sacc[nt][1];
            sacc[nt][2] = __expf(sacc[nt][2] - mn1); rs1 += sacc[nt][2];
            sacc[nt][3] = __expf(sacc[nt][3] - mn1); rs1 += sacc[nt][3];
        }
        rs0 += __shfl_xor_sync(0xffffffffu, rs0, 1);
        rs0 += __shfl_xor_sync(0xffffffffu, rs0, 2);
        rs1 += __shfl_xor_sync(0xffffffffu, rs1, 1);
        rs1 += __shfl_xor_sync(0xffffffffu, rs1, 2);
        l0 = l0 * al0 + rs0;
        l1 = l1 * al1 + rs1;

#pragma unroll
        for (int nt = 0; nt < 16; nt++) {
            oacc[nt][0] *= al0; oacc[nt][1] *= al0;
            oacc[nt][2] *= al1; oacc[nt][3] *= al1;
        }

        // ---- P fp16 A-fragments: direct from C layout ----
        uint32_t ph[8][4];
#pragma unroll
        for (int ks = 0; ks < 8; ks++) {
            ph[ks][0] = pack_h2(sacc[2 * ks][0],     sacc[2 * ks][1]);
            ph[ks][1] = pack_h2(sacc[2 * ks][2],     sacc[2 * ks][3]);
            ph[ks][2] = pack_h2(sacc[2 * ks + 1][0], sacc[2 * ks + 1][1]);
            ph[ks][3] = pack_h2(sacc[2 * ks + 1][2], sacc[2 * ks + 1][3]);
        }

        // ---- O += P @ V  (V frags via ldmatrix.trans) ----
#pragma unroll
        for (int ks = 0; ks < 8; ks++) {
#pragma unroll
            for (int np = 0; np < 8; np++) {
                uint32_t b0, b1, b2, b3;
                ldsm_x4_t(b0, b1, b2, b3,
                          vb + vBase + np * 32 + ks * (16 * AST2 * 2));
                mma_f16(oacc[2 * np],     ph[ks][0], ph[ks][1], ph[ks][2], ph[ks][3], b0, b1);
                mma_f16(oacc[2 * np + 1], ph[ks][0], ph[ks][1], ph[ks][2], ph[ks][3], b2, b3);
            }
        }

        __syncthreads();
        if (kt + 2 < 16) KV_LOAD(kt + 2, kt & 1);
        CP_COMMIT();
    }

    // ---- epilogue -> g_oh (half) ----
    float il0 = 1.f / l0, il1 = 1.f / l1;
    __half* ob = g_oh + ((size_t)b * SEQ + (size_t)qt * 128 + warp * 16) * DIMM + h * HD;
#pragma unroll
    for (int nt = 0; nt < 16; nt++) {
        int c = nt * 8 + q * 2;
        *(uint32_t*)&ob[(size_t)g * DIMM + c] =
            pack_h2(oacc[nt][0] * il0, oacc[nt][1] * il0);
        *(uint32_t*)&ob[(size_t)(g + 8) * DIMM + c] =
            pack_h2(oacc[nt][2] * il1, oacc[nt][3] * il1);
    }
}

// ---------------------------------------------------------------------------
extern "C" void kernel_launch(void* const* d_in, const int* in_sizes, int n_in,
                              void* d_out, int out_size)
{
    const float* x  = (const float*)d_in[0];
    const float* wq = (const float*)d_in[1];
    const float* wk = (const float*)d_in[2];
    const float* wv = (const float*)d_in[3];
    const float* wo = (const float*)d_in[4];
    float* out = (float*)d_out;

    __half *xh, *qh, *kh, *vh, *oh, *wqt, *wkt, *wvt, *wot;
    cudaGetSymbolAddress((void**)&xh,  g_xh);
    cudaGetSymbolAddress((void**)&qh,  g_qh);
    cudaGetSymbolAddress((void**)&kh,  g_kh);
    cudaGetSymbolAddress((void**)&vh,  g_vh);
    cudaGetSymbolAddress((void**)&oh,  g_oh);
    cudaGetSymbolAddress((void**)&wqt, g_wqt);
    cudaGetSymbolAddress((void**)&wkt, g_wkt);
    cudaGetSymbolAddress((void**)&wvt, g_wvt);
    cudaGetSymbolAddress((void**)&wot, g_wot);

    cudaFuncSetAttribute(gemm_f16_kernel<__half>,
                         cudaFuncAttributeMaxDynamicSharedMemorySize, GEMM_SMEM);
    cudaFuncSetAttribute(gemm_f16_kernel<float>,
                         cudaFuncAttributeMaxDynamicSharedMemorySize, GEMM_SMEM);
    cudaFuncSetAttribute(attn_kernel,
                         cudaFuncAttributeMaxDynamicSharedMemorySize, ATTN_SMEM);

    // --- pre-pass: convert x; transpose+convert weights (scale folded in wq) ---
    {
        int n4 = MROWS * DIMM / 4;
        conv_half_kernel<<<(n4 + 255) / 256, 256>>>((const float4*)x, (uint2*)xh, n4);
        const float scale = 0.08838834764831845f;  // 1/sqrt(128)
        dim3 tb(32, 8);
        transpose_half_kernel<<<dim3(DIMM / 32, DIMM / 32), tb>>>(wq, wqt, DIMM, DIMM, scale);
        transpose_half_kernel<<<dim3(KVDIM / 32, DIMM / 32), tb>>>(wk, wkt, DIMM, KVDIM, 1.f);
        transpose_half_kernel<<<dim3(KVDIM / 32, DIMM / 32), tb>>>(wv, wvt, DIMM, KVDIM, 1.f);
        transpose_half_kernel<<<dim3(DIMM / 32, DIMM / 32), tb>>>(wo, wot, DIMM, DIMM, 1.f);
    }

    // --- projections ---
    gemm_f16_kernel<__half><<<dim3(DIMM / 128, MROWS / 128), 256, GEMM_SMEM>>>(
        xh, wqt, qh, MROWS, DIMM, DIMM);
    gemm_f16_kernel<__half><<<dim3(KVDIM / 128, MROWS / 128), 256, GEMM_SMEM>>>(
        xh, wkt, kh, MROWS, KVDIM, DIMM);
    gemm_f16_kernel<__half><<<dim3(KVDIM / 128, MROWS / 128), 256, GEMM_SMEM>>>(
        xh, wvt, vh, MROWS, KVDIM, DIMM);

    // --- attention ---
    attn_kernel<<<dim3(SEQ / 128, NHEAD, NBATCH), 256, ATTN_SMEM>>>();

    // --- output projection (fp32 out) ---
    gemm_f16_kernel<float><<<dim3(DIMM / 128, MROWS / 128), 256, GEMM_SMEM>>>(
        oh, wot, out, MROWS, DIMM, DIMM);
}